// round 14
// baseline (speedup 1.0000x reference)
#include <cuda_runtime.h>
#include <cuda_fp16.h>
#include <cstdint>

#define NROWS 100000
#define DIN   128
#define DH    256
#define DOUT  128
#define KNEI  16
#define EPSBN 1e-5f
#define SLOPE 0.2f

// ---------------- device scratch (no allocations allowed) ------------------------
__device__ float g_y1[(size_t)NROWS * DH];   // layer1 out fp32; reused for raw y3
__device__ float g_y2[(size_t)NROWS * DH];   // layer2 out fp32
__device__ float g_W2e[DH * DH];             // folded W2 (fp32)
__device__ float g_b2e[DH];
__device__ float g_W3e[DOUT * DH];           // folded W3 (fp32)
__device__ float g_b3e[DOUT];
__device__ float g_sum1[DH], g_sq1[DH];
__device__ float g_sum2[DH], g_sq2[DH];
__device__ float g_sum3[DOUT], g_sq3[DOUT];

// ---------------- helpers ---------------------------------------------------------
__device__ __forceinline__ uint32_t smem_u32(const void* p) {
    uint32_t a;
    asm("{ .reg .u64 t; cvta.to.shared.u64 t, %1; cvt.u32.u64 %0, t; }" : "=r"(a) : "l"(p));
    return a;
}
__device__ __forceinline__ void ldsm4(uint32_t* d, uint32_t addr) {
    asm volatile("ldmatrix.sync.aligned.m8n8.x4.shared.b16 {%0,%1,%2,%3}, [%4];"
                 : "=r"(d[0]), "=r"(d[1]), "=r"(d[2]), "=r"(d[3]) : "r"(addr));
}
__device__ __forceinline__ void mma16816(float* c, const uint32_t* a, const uint32_t* b) {
    asm volatile("mma.sync.aligned.m16n8k16.row.col.f32.f16.f16.f32 "
                 "{%0,%1,%2,%3}, {%4,%5,%6,%7}, {%8,%9}, {%0,%1,%2,%3};"
                 : "+f"(c[0]), "+f"(c[1]), "+f"(c[2]), "+f"(c[3])
                 : "r"(a[0]), "r"(a[1]), "r"(a[2]), "r"(a[3]), "r"(b[0]), "r"(b[1]));
}
__device__ __forceinline__ uint32_t pack_h2(__half a, __half b) {
    return (uint32_t)__half_as_ushort(a) | ((uint32_t)__half_as_ushort(b) << 16);
}
// fp16 hi/lo split: x = h + l exactly to ~2^-24
__device__ __forceinline__ void split2(float x, float y, uint32_t& hw, uint32_t& lw) {
    __half a = __float2half_rn(x), b = __float2half_rn(y);
    hw = pack_h2(a, b);
    lw = pack_h2(__float2half_rn(x - __half2float(a)),
                 __float2half_rn(y - __half2float(b)));
}
// fp16 hi only (for B)
__device__ __forceinline__ uint32_t hi2(float x, float y) {
    return pack_h2(__float2half_rn(x), __float2half_rn(y));
}

// ---------------- smem geometry (natural padded layout, ARS=80 proven) -----------
// BM=128, BN=NO (full width), BK=32 fp16.  256 threads, 8 warps: 2m x 4n,
// warp tile 64m x (NO/4)n.  Double-buffered stages.  B: hi plane only (2-pass).
#define ARS   80

// ---------------- tile loaders (fp32 sources, split to fp16 hi/lo inline) --------
template <int KD>
__device__ __forceinline__ void ldgA(float4 v[4], const float* __restrict__ A,
                                     int bm0, int kb, int tid) {
    int r = tid >> 1;                      // 0..127
    int gr = bm0 + r;
    const float* p = A + (size_t)gr * KD + kb * 32 + (tid & 1) * 16;
    bool ok = gr < NROWS;
#pragma unroll
    for (int i = 0; i < 4; i++)
        v[i] = ok ? __ldg((const float4*)(p + i * 4)) : make_float4(0.f, 0.f, 0.f, 0.f);
}

__device__ __forceinline__ void stsA(char* aH, char* aL, const float4 v[4], int tid) {
    int r = tid >> 1;
    int e = (tid & 1) * 32;
#pragma unroll
    for (int i = 0; i < 4; i++) {
        float4 f = v[i];
        uint32_t h0, l0, h1, l1;
        split2(f.x, f.y, h0, l0);
        split2(f.z, f.w, h1, l1);
        int off = r * ARS + e + i * 8;
        *(uint2*)(aH + off) = make_uint2(h0, h1);
        *(uint2*)(aL + off) = make_uint2(l0, l1);
    }
}

template <int KD, int NO>
__device__ __forceinline__ void ldgB(float4 v[NO / 32], const float* __restrict__ W,
                                     int kb, int tid) {
    if (NO == 256) {
        const float* p = W + (size_t)tid * KD + kb * 32;
#pragma unroll
        for (int i = 0; i < NO / 32; i++) v[i] = __ldg((const float4*)(p + i * 4));
    } else {
        int r = tid >> 1;
        const float* p = W + (size_t)r * KD + kb * 32 + (tid & 1) * 16;
#pragma unroll
        for (int i = 0; i < NO / 32; i++) v[i] = __ldg((const float4*)(p + i * 4));
    }
}

template <int NO>
__device__ __forceinline__ void stsB(char* bH, const float4 v[NO / 32], int tid) {
    if (NO == 256) {
#pragma unroll
        for (int i = 0; i < NO / 32; i++) {
            float4 f = v[i];
            int off = tid * ARS + i * 8;
            *(uint2*)(bH + off) = make_uint2(hi2(f.x, f.y), hi2(f.z, f.w));
        }
    } else {
        int r = tid >> 1;
        int e = (tid & 1) * 32;
#pragma unroll
        for (int i = 0; i < NO / 32; i++) {
            float4 f = v[i];
            int off = r * ARS + e + i * 8;
            *(uint2*)(bH + off) = make_uint2(hi2(f.x, f.y), hi2(f.z, f.w));
        }
    }
}

// ---------------- compute one BK=32 stage (ldmatrix fragments, fp16 x2) ----------
// Passes per (mt,nt): Ah*Bh + Al*Bh = A*Bh (error = A*Bl ~ 2^-12 rel).
template <int NT>
__device__ __forceinline__ void computeStage(uint32_t sAh, uint32_t sAl, uint32_t sBh,
                                             float acc[4][NT][4], int wid, int lane) {
    const int mbase = (wid >> 2) * 64;
    const int nbase = (wid & 3) * (NT * 8);
    const int q = lane >> 3, rr = lane & 7;
#pragma unroll
    for (int ks = 0; ks < 2; ks++) {
        uint32_t bh[NT / 2][4];
#pragma unroll
        for (int p = 0; p < NT / 2; p++) {
            uint32_t brow = (uint32_t)(nbase + p * 16 + ((q >> 1) << 3) + rr);
            uint32_t baddr = brow * ARS + (uint32_t)(ks * 32 + (q & 1) * 16);
            ldsm4(bh[p], sBh + baddr);
        }
#pragma unroll
        for (int mt = 0; mt < 4; mt++) {
            uint32_t arow = (uint32_t)(mbase + mt * 16 + ((q & 1) << 3) + rr);
            uint32_t aaddr = arow * ARS + (uint32_t)(ks * 32 + (q >> 1) * 16);
            uint32_t ah[4], al[4];
            ldsm4(ah, sAh + aaddr);
            ldsm4(al, sAl + aaddr);
#pragma unroll
            for (int nt = 0; nt < NT; nt++) {
                uint32_t b0h[2] = {bh[nt >> 1][(nt & 1) * 2], bh[nt >> 1][(nt & 1) * 2 + 1]};
                mma16816(acc[mt][nt], ah, b0h);
                mma16816(acc[mt][nt], al, b0h);
            }
        }
    }
}

// ---------------- GEMM kernel: Y = LeakyReLU(A @ W^T + bias), + col stats --------
template <int KD, int NO, int MODE>
__global__ void __launch_bounds__(256, 1)
gemm_mma2(const float* __restrict__ Xext, const float* __restrict__ bext,
          float* __restrict__ Yext) {
    extern __shared__ char smem[];
    constexpr int NKB = KD / 32;
    constexpr int NT = NO / 32;                 // n-tiles of 8 per warp
    constexpr int AHO = 0, ALO = 10240, BHO = 20480;
    constexpr int STG = BHO + NO * ARS;         // bytes per stage (B hi only)
    constexpr int OEPI = 2 * STG;
    const int tid = threadIdx.x, wid = tid >> 5, lane = tid & 31;
    const int bm0 = blockIdx.x * 128;
    const uint32_t sb = smem_u32(smem);

    const float* A = (MODE == 0) ? Xext : (MODE == 1 ? g_y1 : g_y2);
    const float* Wp = (MODE == 1) ? g_W2e : g_W3e;
    const float* bias = (MODE == 0) ? bext : (MODE == 1 ? g_b2e : g_b3e);
    float* Y    = (MODE == 0) ? g_y1 : (MODE == 1 ? g_y2 : g_y1);  // MODE 2 -> scratch g_y1
    float* gsum = (MODE == 0) ? g_sum1 : (MODE == 1 ? g_sum2 : g_sum3);
    float* gsq  = (MODE == 0) ? g_sq1  : (MODE == 1 ? g_sq2  : g_sq3);
    // For MODE 0, Yext carries W1 (unused as an output there).
    const float* Wsel = (MODE == 0) ? Yext : Wp;

    float* s_bias = (float*)(smem + OEPI);
    float* s_sum  = s_bias + NO;
    float* s_sq   = s_sum + NO;
    if (tid < NO) { s_bias[tid] = __ldg(bias + tid); s_sum[tid] = 0.f; s_sq[tid] = 0.f; }

    float acc[4][NT][4];
#pragma unroll
    for (int i = 0; i < 4; i++)
#pragma unroll
        for (int j = 0; j < NT; j++)
#pragma unroll
            for (int k = 0; k < 4; k++) acc[i][j][k] = 0.f;

    float4 va[4], vb[NO / 32];
    // prologue: stage 0 -> buf0, prefetch stage 1 into regs
    ldgA<KD>(va, A, bm0, 0, tid);
    ldgB<KD, NO>(vb, Wsel, 0, tid);
    stsA(smem + AHO, smem + ALO, va, tid);
    stsB<NO>(smem + BHO, vb, tid);
    if (NKB > 1) {
        ldgA<KD>(va, A, bm0, 1, tid);
        ldgB<KD, NO>(vb, Wsel, 1, tid);
    }
    __syncthreads();

#pragma unroll
    for (int kb = 0; kb < NKB; kb++) {
        const int cur = (kb & 1) * STG;
        const int nxt = ((kb + 1) & 1) * STG;
        if (kb + 1 < NKB) {                 // store stage kb+1 (other buffer)
            stsA(smem + nxt + AHO, smem + nxt + ALO, va, tid);
            stsB<NO>(smem + nxt + BHO, vb, tid);
        }
        if (kb + 2 < NKB) {                 // prefetch stage kb+2 into regs
            ldgA<KD>(va, A, bm0, kb + 2, tid);
            ldgB<KD, NO>(vb, Wsel, kb + 2, tid);
        }
        computeStage<NT>(sb + cur + AHO, sb + cur + ALO, sb + cur + BHO, acc, wid, lane);
        __syncthreads();
    }

    // epilogue: bias + leaky + store + stats
    const int mbase = (wid >> 2) * 64;
    const int wn = (wid & 3) * (NT * 8);
    float csum[NT][2], csq[NT][2];
#pragma unroll
    for (int nt = 0; nt < NT; nt++) { csum[nt][0] = csum[nt][1] = 0.f; csq[nt][0] = csq[nt][1] = 0.f; }

#pragma unroll
    for (int mt = 0; mt < 4; mt++) {
        int r0 = bm0 + mbase + mt * 16 + (lane >> 2);
        int r1 = r0 + 8;
#pragma unroll
        for (int nt = 0; nt < NT; nt++) {
            int jl = wn + nt * 8 + (lane & 3) * 2;
            float b0 = s_bias[jl], b1 = s_bias[jl + 1];
            float x0 = acc[mt][nt][0] + b0; x0 = x0 > 0.f ? x0 : SLOPE * x0;
            float x1 = acc[mt][nt][1] + b1; x1 = x1 > 0.f ? x1 : SLOPE * x1;
            float x2 = acc[mt][nt][2] + b0; x2 = x2 > 0.f ? x2 : SLOPE * x2;
            float x3 = acc[mt][nt][3] + b1; x3 = x3 > 0.f ? x3 : SLOPE * x3;
            if (r0 < NROWS) {
                *(float2*)(Y + (size_t)r0 * NO + jl) = make_float2(x0, x1);
                csum[nt][0] += x0; csum[nt][1] += x1;
                csq[nt][0] += x0 * x0; csq[nt][1] += x1 * x1;
            }
            if (r1 < NROWS) {
                *(float2*)(Y + (size_t)r1 * NO + jl) = make_float2(x2, x3);
                csum[nt][0] += x2; csum[nt][1] += x3;
                csq[nt][0] += x2 * x2; csq[nt][1] += x3 * x3;
            }
        }
    }
#pragma unroll
    for (int nt = 0; nt < NT; nt++)
#pragma unroll
        for (int p = 0; p < 2; p++) {
            float s = csum[nt][p], q = csq[nt][p];
            s += __shfl_xor_sync(0xFFFFFFFFu, s, 4);  q += __shfl_xor_sync(0xFFFFFFFFu, q, 4);
            s += __shfl_xor_sync(0xFFFFFFFFu, s, 8);  q += __shfl_xor_sync(0xFFFFFFFFu, q, 8);
            s += __shfl_xor_sync(0xFFFFFFFFu, s, 16); q += __shfl_xor_sync(0xFFFFFFFFu, q, 16);
            if (lane < 4) {
                int col = wn + nt * 8 + lane * 2 + p;
                atomicAdd(&s_sum[col], s);
                atomicAdd(&s_sq[col], q);
            }
        }
    __syncthreads();
    if (tid < NO) {
        atomicAdd(gsum + tid, s_sum[tid]);
        atomicAdd(gsq + tid, s_sq[tid]);
    }
}

// ---------------- small kernels --------------------------------------------------
__global__ void zero_stats_kernel() {
    int t = threadIdx.x;  // 256
    g_sum1[t] = 0.f; g_sq1[t] = 0.f;
    g_sum2[t] = 0.f; g_sq2[t] = 0.f;
    if (t < DOUT) { g_sum3[t] = 0.f; g_sq3[t] = 0.f; }
}

__global__ void fold_kernel(const float* __restrict__ W, const float* __restrict__ b,
                            const float* __restrict__ g, const float* __restrict__ beta,
                            int layer) {
    int j = threadIdx.x;   // 256 = DH
    int o = blockIdx.x;
    const float* sum = (layer == 1) ? g_sum1 : g_sum2;
    const float* sq  = (layer == 1) ? g_sq1  : g_sq2;
    float* We        = (layer == 1) ? g_W2e  : g_W3e;
    float* be        = (layer == 1) ? g_b2e  : g_b3e;

    const float invN = 1.0f / (float)NROWS;
    float mean = sum[j] * invN;
    float var  = sq[j] * invN - mean * mean;
    float a = g[j] * rsqrtf(var + EPSBN);
    float c = beta[j] - mean * a;
    float w = W[o * DH + j];
    We[o * DH + j] = w * a;

    __shared__ float red[DH];
    red[j] = w * c;
    __syncthreads();
    for (int s = DH / 2; s > 0; s >>= 1) {
        if (j < s) red[j] += red[j + s];
        __syncthreads();
    }
    if (j == 0) be[o] = b[o] + red[0];
}

// fused: BN3 coefficients inline + f = y3*a+c + node_update = affine(mean neighbor y3)
// y3 = g_y1 referenced from DEVICE scope (host can't take __device__ addresses).
__global__ void gather_affine_kernel(const int* __restrict__ nidx,
                                     const float* __restrict__ g3,
                                     const float* __restrict__ be3,
                                     float* __restrict__ fout,
                                     float* __restrict__ out) {
    __shared__ int sidx[2 * KNEI];
    int tid = threadIdx.x;              // 256 threads = 2 nodes
    int node0 = blockIdx.x * 2;
    if (tid < 2 * KNEI) sidx[tid] = nidx[(size_t)node0 * KNEI + tid];
    __syncthreads();
    int local = tid >> 7;
    int j = tid & (DOUT - 1);
    int node = node0 + local;

    const float invN = 1.0f / (float)NROWS;
    float mean = g_sum3[j] * invN;
    float var  = g_sq3[j] * invN - mean * mean;
    float a = __ldg(g3 + j) * rsqrtf(var + EPSBN);
    float c = __ldg(be3 + j) - mean * a;
    const float* y3 = g_y1;             // device-scope reference (valid)

    fout[(size_t)node * DOUT + j] = y3[(size_t)node * DOUT + j] * a + c;

    float s = 0.f;
#pragma unroll
    for (int k = 0; k < KNEI; k++) {
        int nk = sidx[local * KNEI + k];
        s += __ldg(y3 + (size_t)nk * DOUT + j);
    }
    out[(size_t)node * DOUT + j] = (s * (1.0f / KNEI)) * a + c;
}

// ---------------------------------------------------------------------------------
extern "C" void kernel_launch(void* const* d_in, const int* in_sizes, int n_in,
                              void* d_out, int out_size) {
    const float* X   = (const float*)d_in[0];
    const int*   nid = (const int*)d_in[1];
    const float* W1  = (const float*)d_in[3];
    const float* b1  = (const float*)d_in[4];
    const float* g1  = (const float*)d_in[5];
    const float* be1 = (const float*)d_in[6];
    const float* W2  = (const float*)d_in[7];
    const float* b2  = (const float*)d_in[8];
    const float* g2  = (const float*)d_in[9];
    const float* be2 = (const float*)d_in[10];
    const float* W3  = (const float*)d_in[11];
    const float* b3  = (const float*)d_in[12];
    const float* g3  = (const float*)d_in[13];
    const float* be3 = (const float*)d_in[14];

    float* out  = (float*)d_out;                   // node_update [N, DOUT]
    float* fbuf = out + (size_t)NROWS * DOUT;      // f           [N, DOUT]

    const int mblocks = (NROWS + 127) / 128;       // 782
    const int SM256 = 2 * (20480 + 256 * ARS) + 3 * 256 * 4;   // 84992
    const int SM128 = 2 * (20480 + 128 * ARS) + 3 * 128 * 4;   // 63488

    cudaFuncSetAttribute(gemm_mma2<128, 256, 0>, cudaFuncAttributeMaxDynamicSharedMemorySize, SM256);
    cudaFuncSetAttribute(gemm_mma2<256, 256, 1>, cudaFuncAttributeMaxDynamicSharedMemorySize, SM256);
    cudaFuncSetAttribute(gemm_mma2<256, 128, 2>, cudaFuncAttributeMaxDynamicSharedMemorySize, SM128);

    zero_stats_kernel<<<1, 256>>>();

    // layer 1: X @ W1^T -> g_y1 (+stats1).  W1 passed via 3rd arg (unused as output in MODE 0)
    gemm_mma2<128, 256, 0><<<mblocks, 256, SM256>>>(X, b1, (float*)W1);
    fold_kernel<<<DH, DH>>>(W2, b2, g1, be1, 1);
    gemm_mma2<256, 256, 1><<<mblocks, 256, SM256>>>(nullptr, nullptr, nullptr);
    fold_kernel<<<DOUT, DH>>>(W3, b3, g2, be2, 2);
    // layer 3: g_y2 @ W3e^T -> g_y1 scratch (raw y3, +stats3)
    gemm_mma2<256, 128, 2><<<mblocks, 256, SM128>>>(nullptr, nullptr, nullptr);

    // fused BN3 coefficients + affine + neighbor-mean gather
    gather_affine_kernel<<<NROWS / 2, 256>>>(nid, g3, be3, fbuf, out);
}

// round 15
// speedup vs baseline: 1.3318x; 1.3318x over previous
#include <cuda_runtime.h>
#include <cuda_bf16.h>
#include <cstdint>

#define NROWS 100000
#define DIN   128
#define DH    256
#define DOUT  128
#define KNEI  16
#define EPSBN 1e-5f
#define SLOPE 0.2f

// ---------------- device scratch (no allocations allowed) ------------------------
__device__ float g_y1[(size_t)NROWS * DH];   // layer1 out fp32; reused for raw y3
__device__ float g_y2[(size_t)NROWS * DH];   // layer2 out fp32
__device__ __nv_bfloat16 g_W1h[DH * DIN],  g_W1l[DH * DIN];
__device__ __nv_bfloat16 g_W2h[DH * DH],   g_W2l[DH * DH];
__device__ __nv_bfloat16 g_W3h[DOUT * DH], g_W3l[DOUT * DH];
__device__ float g_b2e[DH], g_b3e[DOUT];
__device__ float g_sum1[DH], g_sq1[DH];
__device__ float g_sum2[DH], g_sq2[DH];
__device__ float g_sum3[DOUT], g_sq3[DOUT];

// ---------------- helpers ---------------------------------------------------------
__device__ __forceinline__ uint32_t smem_u32(const void* p) {
    uint32_t a;
    asm("{ .reg .u64 t; cvta.to.shared.u64 t, %1; cvt.u32.u64 %0, t; }" : "=r"(a) : "l"(p));
    return a;
}
__device__ __forceinline__ void ldsm4(uint32_t* d, uint32_t addr) {
    asm volatile("ldmatrix.sync.aligned.m8n8.x4.shared.b16 {%0,%1,%2,%3}, [%4];"
                 : "=r"(d[0]), "=r"(d[1]), "=r"(d[2]), "=r"(d[3]) : "r"(addr));
}
__device__ __forceinline__ void mma16816(float* c, const uint32_t* a, const uint32_t* b) {
    asm volatile("mma.sync.aligned.m16n8k16.row.col.f32.bf16.bf16.f32 "
                 "{%0,%1,%2,%3}, {%4,%5,%6,%7}, {%8,%9}, {%0,%1,%2,%3};"
                 : "+f"(c[0]), "+f"(c[1]), "+f"(c[2]), "+f"(c[3])
                 : "r"(a[0]), "r"(a[1]), "r"(a[2]), "r"(a[3]), "r"(b[0]), "r"(b[1]));
}
__device__ __forceinline__ uint32_t pack_bf2(float x, float y) {
    __nv_bfloat16 a = __float2bfloat16(x), b = __float2bfloat16(y);
    return (uint32_t)__bfloat16_as_ushort(a) | ((uint32_t)__bfloat16_as_ushort(b) << 16);
}
__device__ __forceinline__ void split2(float x, float y, uint32_t& hw, uint32_t& lw) {
    __nv_bfloat16 a = __float2bfloat16(x), b = __float2bfloat16(y);
    hw = (uint32_t)__bfloat16_as_ushort(a) | ((uint32_t)__bfloat16_as_ushort(b) << 16);
    lw = pack_bf2(x - __bfloat162float(a), y - __bfloat162float(b));
}
__device__ __forceinline__ void cpasync16(uint32_t dst, const void* src) {
    asm volatile("cp.async.cg.shared.global [%0], [%1], 16;" :: "r"(dst), "l"(src));
}
__device__ __forceinline__ void cp_commit() {
    asm volatile("cp.async.commit_group;" ::: "memory");
}
__device__ __forceinline__ void cp_wait0() {
    asm volatile("cp.async.wait_group 0;" ::: "memory");
}
__device__ __forceinline__ void cp_wait1() {
    asm volatile("cp.async.wait_group 1;" ::: "memory");
}

// ---------------- smem geometry ---------------------------------------------------
// BM=128, BN=NO (full width), BK=64 bf16.  Row stride 144 B (64 bf16 + 16B pad):
// 8 rows @ 36-word stride hit distinct bank groups -> ldmatrix conflict-free.
// 256 threads, 8 warps: 2m x 4n, warp tile 64m x (NO/4)n.  2 cp.async stages.
#define ARS   144

// ---------------- A loader (fp32 source, split to bf16 hi/lo inline) -------------
template <int KD>
__device__ __forceinline__ void ldgA(float4 v[8], const float* __restrict__ A,
                                     int bm0, int kb, int tid) {
    int r = tid >> 1;                      // 0..127
    int gr = bm0 + r;
    const float* p = A + (size_t)gr * KD + kb * 64 + (tid & 1) * 32;
    bool ok = gr < NROWS;
#pragma unroll
    for (int i = 0; i < 8; i++)
        v[i] = ok ? __ldg((const float4*)(p + i * 4)) : make_float4(0.f, 0.f, 0.f, 0.f);
}

__device__ __forceinline__ void stsA(char* aH, char* aL, const float4 v[8], int tid) {
    int r = tid >> 1;
    int e = (tid & 1) * 64;
#pragma unroll
    for (int i = 0; i < 8; i++) {
        float4 f = v[i];
        uint32_t h0, l0, h1, l1;
        split2(f.x, f.y, h0, l0);
        split2(f.z, f.w, h1, l1);
        int off = r * ARS + e + i * 8;
        *(uint2*)(aH + off) = make_uint2(h0, h1);
        *(uint2*)(aL + off) = make_uint2(l0, l1);
    }
}

// ---------------- B loader: cp.async from pre-split bf16 planes ------------------
// B tile: NO rows x 64 bf16 (128 B/row = 8 x 16B chunks).
template <int KD, int NO>
__device__ __forceinline__ void cpB(uint32_t bH, uint32_t bL,
                                    const __nv_bfloat16* __restrict__ Wh,
                                    const __nv_bfloat16* __restrict__ Wl,
                                    int kb, int tid) {
#pragma unroll
    for (int k = 0; k < NO / 32; k++) {
        int c = tid + k * 256;
        int row = c >> 3, col = c & 7;
        size_t src = (size_t)row * KD + kb * 64 + col * 8;
        uint32_t dst = (uint32_t)row * ARS + col * 16;
        cpasync16(bH + dst, Wh + src);
        cpasync16(bL + dst, Wl + src);
    }
}

// ---------------- compute one BK=64 stage (ldmatrix fragments, bf16x3) -----------
template <int NT>
__device__ __forceinline__ void computeStage(uint32_t sAh, uint32_t sAl,
                                             uint32_t sBh, uint32_t sBl,
                                             float acc[4][NT][4], int wid, int lane) {
    const int mbase = (wid >> 2) * 64;
    const int nbase = (wid & 3) * (NT * 8);
    const int q = lane >> 3, rr = lane & 7;
#pragma unroll
    for (int ks = 0; ks < 4; ks++) {
        uint32_t bh[NT / 2][4], bl[NT / 2][4];
#pragma unroll
        for (int p = 0; p < NT / 2; p++) {
            uint32_t brow = (uint32_t)(nbase + p * 16 + ((q >> 1) << 3) + rr);
            uint32_t baddr = brow * ARS + (uint32_t)(ks * 32 + (q & 1) * 16);
            ldsm4(bh[p], sBh + baddr);
            ldsm4(bl[p], sBl + baddr);
        }
#pragma unroll
        for (int mt = 0; mt < 4; mt++) {
            uint32_t arow = (uint32_t)(mbase + mt * 16 + ((q & 1) << 3) + rr);
            uint32_t aaddr = arow * ARS + (uint32_t)(ks * 32 + (q >> 1) * 16);
            uint32_t ah[4], al[4];
            ldsm4(ah, sAh + aaddr);
            ldsm4(al, sAl + aaddr);
#pragma unroll
            for (int nt = 0; nt < NT; nt++) {
                uint32_t b0h[2] = {bh[nt >> 1][(nt & 1) * 2], bh[nt >> 1][(nt & 1) * 2 + 1]};
                uint32_t b0l[2] = {bl[nt >> 1][(nt & 1) * 2], bl[nt >> 1][(nt & 1) * 2 + 1]};
                mma16816(acc[mt][nt], ah, b0h);
                mma16816(acc[mt][nt], al, b0h);
                mma16816(acc[mt][nt], ah, b0l);
            }
        }
    }
}

// ---------------- GEMM kernel: Y = LeakyReLU(A @ W^T + bias), + col stats --------
template <int KD, int NO, int MODE>
__global__ void __launch_bounds__(256, 1)
gemm_mma3(const float* __restrict__ Xext, const float* __restrict__ bext) {
    extern __shared__ char smem[];
    constexpr int NKB = KD / 64;
    constexpr int NT = NO / 32;                 // n-tiles of 8 per warp
    constexpr int AHO = 0, ALO = 128 * ARS, BHO = 2 * 128 * ARS;
    constexpr int BLO = BHO + NO * ARS;
    constexpr int STG = BHO + 2 * NO * ARS;     // bytes per stage
    constexpr int OEPI = 2 * STG;
    const int tid = threadIdx.x, wid = tid >> 5, lane = tid & 31;
    const int bm0 = blockIdx.x * 128;
    const uint32_t sb = smem_u32(smem);

    const float* A = (MODE == 0) ? Xext : (MODE == 1 ? g_y1 : g_y2);
    const __nv_bfloat16* Wh = (MODE == 0) ? g_W1h : (MODE == 1 ? g_W2h : g_W3h);
    const __nv_bfloat16* Wl = (MODE == 0) ? g_W1l : (MODE == 1 ? g_W2l : g_W3l);
    const float* bias = (MODE == 0) ? bext : (MODE == 1 ? g_b2e : g_b3e);
    float* Y    = (MODE == 0) ? g_y1 : (MODE == 1 ? g_y2 : g_y1);  // MODE 2 -> scratch g_y1
    float* gsum = (MODE == 0) ? g_sum1 : (MODE == 1 ? g_sum2 : g_sum3);
    float* gsq  = (MODE == 0) ? g_sq1  : (MODE == 1 ? g_sq2  : g_sq3);

    float* s_bias = (float*)(smem + OEPI);
    float* s_sum  = s_bias + NO;
    float* s_sq   = s_sum + NO;
    if (tid < NO) { s_bias[tid] = __ldg(bias + tid); s_sum[tid] = 0.f; s_sq[tid] = 0.f; }

    float acc[4][NT][4];
#pragma unroll
    for (int i = 0; i < 4; i++)
#pragma unroll
        for (int j = 0; j < NT; j++)
#pragma unroll
            for (int k = 0; k < 4; k++) acc[i][j][k] = 0.f;

    float4 va[8];
    // prologue: B stages 0,1 in flight; A stage 0 to smem; A stage 1 in regs
    ldgA<KD>(va, A, bm0, 0, tid);
    cpB<KD, NO>(sb + BHO, sb + BLO, Wh, Wl, 0, tid);
    cp_commit();
    if (NKB > 1) {
        cpB<KD, NO>(sb + STG + BHO, sb + STG + BLO, Wh, Wl, 1, tid);
        cp_commit();
    }
    stsA(smem + AHO, smem + ALO, va, tid);
    if (NKB > 1) ldgA<KD>(va, A, bm0, 1, tid);

#pragma unroll
    for (int kb = 0; kb < NKB; kb++) {
        const int cur = (kb & 1) * STG;
        const int nxt = ((kb + 1) & 1) * STG;
        if (kb + 1 < NKB) cp_wait1(); else cp_wait0();
        __syncthreads();
        if (kb + 1 < NKB) stsA(smem + nxt + AHO, smem + nxt + ALO, va, tid);
        if (kb + 2 < NKB) ldgA<KD>(va, A, bm0, kb + 2, tid);
        computeStage<NT>(sb + cur + AHO, sb + cur + ALO, sb + cur + BHO, sb + cur + BLO,
                         acc, wid, lane);
        __syncthreads();
        if (kb + 2 < NKB) {
            cpB<KD, NO>(sb + cur + BHO, sb + cur + BLO, Wh, Wl, kb + 2, tid);
            cp_commit();
        }
    }

    // epilogue: bias + leaky + store + stats
    const int mbase = (wid >> 2) * 64;
    const int wn = (wid & 3) * (NT * 8);
    float csum[NT][2], csq[NT][2];
#pragma unroll
    for (int nt = 0; nt < NT; nt++) { csum[nt][0] = csum[nt][1] = 0.f; csq[nt][0] = csq[nt][1] = 0.f; }

#pragma unroll
    for (int mt = 0; mt < 4; mt++) {
        int r0 = bm0 + mbase + mt * 16 + (lane >> 2);
        int r1 = r0 + 8;
#pragma unroll
        for (int nt = 0; nt < NT; nt++) {
            int jl = wn + nt * 8 + (lane & 3) * 2;
            float b0 = s_bias[jl], b1 = s_bias[jl + 1];
            float x0 = acc[mt][nt][0] + b0; x0 = x0 > 0.f ? x0 : SLOPE * x0;
            float x1 = acc[mt][nt][1] + b1; x1 = x1 > 0.f ? x1 : SLOPE * x1;
            float x2 = acc[mt][nt][2] + b0; x2 = x2 > 0.f ? x2 : SLOPE * x2;
            float x3 = acc[mt][nt][3] + b1; x3 = x3 > 0.f ? x3 : SLOPE * x3;
            if (r0 < NROWS) {
                *(float2*)(Y + (size_t)r0 * NO + jl) = make_float2(x0, x1);
                csum[nt][0] += x0; csum[nt][1] += x1;
                csq[nt][0] += x0 * x0; csq[nt][1] += x1 * x1;
            }
            if (r1 < NROWS) {
                *(float2*)(Y + (size_t)r1 * NO + jl) = make_float2(x2, x3);
                csum[nt][0] += x2; csum[nt][1] += x3;
                csq[nt][0] += x2 * x2; csq[nt][1] += x3 * x3;
            }
        }
    }
#pragma unroll
    for (int nt = 0; nt < NT; nt++)
#pragma unroll
        for (int p = 0; p < 2; p++) {
            float s = csum[nt][p], q = csq[nt][p];
            s += __shfl_xor_sync(0xFFFFFFFFu, s, 4);  q += __shfl_xor_sync(0xFFFFFFFFu, q, 4);
            s += __shfl_xor_sync(0xFFFFFFFFu, s, 8);  q += __shfl_xor_sync(0xFFFFFFFFu, q, 8);
            s += __shfl_xor_sync(0xFFFFFFFFu, s, 16); q += __shfl_xor_sync(0xFFFFFFFFu, q, 16);
            if (lane < 4) {
                int col = wn + nt * 8 + lane * 2 + p;
                atomicAdd(&s_sum[col], s);
                atomicAdd(&s_sq[col], q);
            }
        }
    __syncthreads();
    if (tid < NO) {
        atomicAdd(gsum + tid, s_sum[tid]);
        atomicAdd(gsq + tid, s_sq[tid]);
    }
}

// ---------------- small kernels --------------------------------------------------
__global__ void zero_stats_kernel() {
    int t = threadIdx.x;  // 256
    g_sum1[t] = 0.f; g_sq1[t] = 0.f;
    g_sum2[t] = 0.f; g_sq2[t] = 0.f;
    if (t < DOUT) { g_sum3[t] = 0.f; g_sq3[t] = 0.f; }
}

__global__ void splitW1_kernel(const float* __restrict__ W1) {
    int i = blockIdx.x * 256 + threadIdx.x;
    if (i < DH * DIN) {
        float w = W1[i];
        __nv_bfloat16 h = __float2bfloat16(w);
        g_W1h[i] = h;
        g_W1l[i] = __float2bfloat16(w - __bfloat162float(h));
    }
}

// fold BN affine of previous layer into next layer's weights, emit bf16 hi/lo planes.
__global__ void fold_kernel(const float* __restrict__ W, const float* __restrict__ b,
                            const float* __restrict__ g, const float* __restrict__ beta,
                            int layer) {
    int j = threadIdx.x;   // 256 = DH
    int o = blockIdx.x;
    const float* sum = (layer == 1) ? g_sum1 : g_sum2;
    const float* sq  = (layer == 1) ? g_sq1  : g_sq2;

    const float invN = 1.0f / (float)NROWS;
    float mean = sum[j] * invN;
    float var  = sq[j] * invN - mean * mean;
    float a = g[j] * rsqrtf(var + EPSBN);
    float c = beta[j] - mean * a;
    float w = W[o * DH + j];
    float wa = w * a;
    __nv_bfloat16 h = __float2bfloat16(wa);
    __nv_bfloat16 l = __float2bfloat16(wa - __bfloat162float(h));
    if (layer == 1) { g_W2h[o * DH + j] = h; g_W2l[o * DH + j] = l; }
    else            { g_W3h[o * DH + j] = h; g_W3l[o * DH + j] = l; }

    __shared__ float red[DH];
    red[j] = w * c;
    __syncthreads();
    for (int s = DH / 2; s > 0; s >>= 1) {
        if (j < s) red[j] += red[j + s];
        __syncthreads();
    }
    if (j == 0) {
        float be = b[o] + red[0];
        if (layer == 1) g_b2e[o] = be; else g_b3e[o] = be;
    }
}

// fused: BN3 coefficients inline + f = y3*a+c + node_update = affine(mean neighbor y3)
// y3 = g_y1 referenced from DEVICE scope (host can't take __device__ addresses).
__global__ void gather_affine_kernel(const int* __restrict__ nidx,
                                     const float* __restrict__ g3,
                                     const float* __restrict__ be3,
                                     float* __restrict__ fout,
                                     float* __restrict__ out) {
    __shared__ int sidx[2 * KNEI];
    int tid = threadIdx.x;              // 256 threads = 2 nodes
    int node0 = blockIdx.x * 2;
    if (tid < 2 * KNEI) sidx[tid] = nidx[(size_t)node0 * KNEI + tid];
    __syncthreads();
    int local = tid >> 7;
    int j = tid & (DOUT - 1);
    int node = node0 + local;

    const float invN = 1.0f / (float)NROWS;
    float mean = g_sum3[j] * invN;
    float var  = g_sq3[j] * invN - mean * mean;
    float a = __ldg(g3 + j) * rsqrtf(var + EPSBN);
    float c = __ldg(be3 + j) - mean * a;
    const float* y3 = g_y1;             // device-scope reference (valid)

    fout[(size_t)node * DOUT + j] = y3[(size_t)node * DOUT + j] * a + c;

    float s = 0.f;
#pragma unroll
    for (int k = 0; k < KNEI; k++) {
        int nk = sidx[local * KNEI + k];
        s += __ldg(y3 + (size_t)nk * DOUT + j);
    }
    out[(size_t)node * DOUT + j] = (s * (1.0f / KNEI)) * a + c;
}

// ---------------------------------------------------------------------------------
extern "C" void kernel_launch(void* const* d_in, const int* in_sizes, int n_in,
                              void* d_out, int out_size) {
    const float* X   = (const float*)d_in[0];
    const int*   nid = (const int*)d_in[1];
    const float* W1  = (const float*)d_in[3];
    const float* b1  = (const float*)d_in[4];
    const float* g1  = (const float*)d_in[5];
    const float* be1 = (const float*)d_in[6];
    const float* W2  = (const float*)d_in[7];
    const float* b2  = (const float*)d_in[8];
    const float* g2  = (const float*)d_in[9];
    const float* be2 = (const float*)d_in[10];
    const float* W3  = (const float*)d_in[11];
    const float* b3  = (const float*)d_in[12];
    const float* g3  = (const float*)d_in[13];
    const float* be3 = (const float*)d_in[14];

    float* out  = (float*)d_out;                   // node_update [N, DOUT]
    float* fbuf = out + (size_t)NROWS * DOUT;      // f           [N, DOUT]

    const int mblocks = (NROWS + 127) / 128;       // 782
    // stage = 2*128*ARS (A) + 2*NO*ARS (B)
    const int SM256 = 2 * (2 * 128 * ARS + 2 * 256 * ARS) + 3 * 256 * 4;   // 224256
    const int SM128 = 2 * (2 * 128 * ARS + 2 * 128 * ARS) + 3 * 128 * 4;   // 149000ish

    cudaFuncSetAttribute(gemm_mma3<128, 256, 0>, cudaFuncAttributeMaxDynamicSharedMemorySize, SM256);
    cudaFuncSetAttribute(gemm_mma3<256, 256, 1>, cudaFuncAttributeMaxDynamicSharedMemorySize, SM256);
    cudaFuncSetAttribute(gemm_mma3<256, 128, 2>, cudaFuncAttributeMaxDynamicSharedMemorySize, SM128);

    zero_stats_kernel<<<1, 256>>>();
    splitW1_kernel<<<(DH * DIN + 255) / 256, 256>>>(W1);

    // layer 1: X @ W1^T -> g_y1 (+stats1)
    gemm_mma3<128, 256, 0><<<mblocks, 256, SM256>>>(X, b1);
    fold_kernel<<<DH, DH>>>(W2, b2, g1, be1, 1);
    gemm_mma3<256, 256, 1><<<mblocks, 256, SM256>>>(nullptr, nullptr);
    fold_kernel<<<DOUT, DH>>>(W3, b3, g2, be2, 2);
    // layer 3: g_y2 @ W3e^T -> g_y1 scratch (raw y3, +stats3)
    gemm_mma3<256, 128, 2><<<mblocks, 256, SM128>>>(nullptr, nullptr);

    // fused BN3 coefficients + affine + neighbor-mean gather
    gather_affine_kernel<<<NROWS / 2, 256>>>(nid, g3, be3, fbuf, out);
}

// round 16
// speedup vs baseline: 1.4776x; 1.1094x over previous
#include <cuda_runtime.h>
#include <cuda_bf16.h>
#include <cstdint>

#define NROWS 100000
#define NPAD  100096
#define DIN   128
#define DH    256
#define DOUT  128
#define KNEI  16
#define EPSBN 1e-5f
#define SLOPE 0.2f

// ---------------- device scratch (no allocations allowed) ------------------------
__device__ float g_y1[(size_t)NROWS * DH];   // fp32 scratch: raw y3 for gather
__device__ __nv_bfloat16 g_y1h[(size_t)NPAD * DH], g_y1l[(size_t)NPAD * DH];
__device__ __nv_bfloat16 g_y2h[(size_t)NPAD * DH], g_y2l[(size_t)NPAD * DH];
__device__ __nv_bfloat16 g_W1h[DH * DIN],  g_W1l[DH * DIN];
__device__ __nv_bfloat16 g_W2h[DH * DH],   g_W2l[DH * DH];
__device__ __nv_bfloat16 g_W3h[DOUT * DH], g_W3l[DOUT * DH];
__device__ float g_b2e[DH], g_b3e[DOUT];
__device__ float g_sum1[DH], g_sq1[DH];
__device__ float g_sum2[DH], g_sq2[DH];
__device__ float g_sum3[DOUT], g_sq3[DOUT];

// ---------------- helpers ---------------------------------------------------------
__device__ __forceinline__ uint32_t smem_u32(const void* p) {
    uint32_t a;
    asm("{ .reg .u64 t; cvta.to.shared.u64 t, %1; cvt.u32.u64 %0, t; }" : "=r"(a) : "l"(p));
    return a;
}
__device__ __forceinline__ void ldsm4(uint32_t* d, uint32_t addr) {
    asm volatile("ldmatrix.sync.aligned.m8n8.x4.shared.b16 {%0,%1,%2,%3}, [%4];"
                 : "=r"(d[0]), "=r"(d[1]), "=r"(d[2]), "=r"(d[3]) : "r"(addr));
}
__device__ __forceinline__ void mma16816(float* c, const uint32_t* a, const uint32_t* b) {
    asm volatile("mma.sync.aligned.m16n8k16.row.col.f32.bf16.bf16.f32 "
                 "{%0,%1,%2,%3}, {%4,%5,%6,%7}, {%8,%9}, {%0,%1,%2,%3};"
                 : "+f"(c[0]), "+f"(c[1]), "+f"(c[2]), "+f"(c[3])
                 : "r"(a[0]), "r"(a[1]), "r"(a[2]), "r"(a[3]), "r"(b[0]), "r"(b[1]));
}
__device__ __forceinline__ uint32_t pack_bf2(float x, float y) {
    __nv_bfloat16 a = __float2bfloat16(x), b = __float2bfloat16(y);
    return (uint32_t)__bfloat16_as_ushort(a) | ((uint32_t)__bfloat16_as_ushort(b) << 16);
}
__device__ __forceinline__ void split2(float x, float y, uint32_t& hw, uint32_t& lw) {
    __nv_bfloat16 a = __float2bfloat16(x), b = __float2bfloat16(y);
    hw = (uint32_t)__bfloat16_as_ushort(a) | ((uint32_t)__bfloat16_as_ushort(b) << 16);
    lw = pack_bf2(x - __bfloat162float(a), y - __bfloat162float(b));
}
__device__ __forceinline__ void cpasync16(uint32_t dst, const void* src) {
    asm volatile("cp.async.cg.shared.global [%0], [%1], 16;" :: "r"(dst), "l"(src));
}
__device__ __forceinline__ void cp_commit() {
    asm volatile("cp.async.commit_group;" ::: "memory");
}
__device__ __forceinline__ void cp_wait0() {
    asm volatile("cp.async.wait_group 0;" ::: "memory");
}
__device__ __forceinline__ void cp_wait1() {
    asm volatile("cp.async.wait_group 1;" ::: "memory");
}

// ---------------- smem geometry ---------------------------------------------------
// BM=128, BN=NO (full width), BK=64 bf16.  Row stride 144 B (64 bf16 + 16B pad).
// 256 threads, 8 warps: 2m x 4n, warp tile 64m x (NO/4)n.  2 cp.async stages.
#define ARS   144

// ---------------- A path for MODE 0 (fp32 X, reg split) --------------------------
template <int KD>
__device__ __forceinline__ void ldgA(float4 v[8], const float* __restrict__ A,
                                     int bm0, int kb, int tid) {
    int r = tid >> 1;                      // 0..127
    int gr = bm0 + r;
    const float* p = A + (size_t)gr * KD + kb * 64 + (tid & 1) * 32;
    bool ok = gr < NROWS;
#pragma unroll
    for (int i = 0; i < 8; i++)
        v[i] = ok ? __ldg((const float4*)(p + i * 4)) : make_float4(0.f, 0.f, 0.f, 0.f);
}

__device__ __forceinline__ void stsA(char* aH, char* aL, const float4 v[8], int tid) {
    int r = tid >> 1;
    int e = (tid & 1) * 64;
#pragma unroll
    for (int i = 0; i < 8; i++) {
        float4 f = v[i];
        uint32_t h0, l0, h1, l1;
        split2(f.x, f.y, h0, l0);
        split2(f.z, f.w, h1, l1);
        int off = r * ARS + e + i * 8;
        *(uint2*)(aH + off) = make_uint2(h0, h1);
        *(uint2*)(aL + off) = make_uint2(l0, l1);
    }
}

// ---------------- cp.async tile loader: R rows x 64 bf16 from a plane ------------
template <int R, int KD>
__device__ __forceinline__ void cpTile(uint32_t dH, uint32_t dL,
                                       const __nv_bfloat16* __restrict__ H,
                                       const __nv_bfloat16* __restrict__ L,
                                       size_t row0, int kb, int tid) {
#pragma unroll
    for (int k = 0; k < R / 32; k++) {
        int c = tid + k * 256;
        int row = c >> 3, col = c & 7;
        size_t src = (row0 + row) * KD + (size_t)kb * 64 + col * 8;
        uint32_t dst = (uint32_t)row * ARS + col * 16;
        cpasync16(dH + dst, H + src);
        cpasync16(dL + dst, L + src);
    }
}

// ---------------- compute one BK=64 stage (ldmatrix fragments, bf16x3) -----------
template <int NT>
__device__ __forceinline__ void computeStage(uint32_t sAh, uint32_t sAl,
                                             uint32_t sBh, uint32_t sBl,
                                             float acc[4][NT][4], int wid, int lane) {
    const int mbase = (wid >> 2) * 64;
    const int nbase = (wid & 3) * (NT * 8);
    const int q = lane >> 3, rr = lane & 7;
#pragma unroll
    for (int ks = 0; ks < 4; ks++) {
        uint32_t bh[NT / 2][4], bl[NT / 2][4];
#pragma unroll
        for (int p = 0; p < NT / 2; p++) {
            uint32_t brow = (uint32_t)(nbase + p * 16 + ((q >> 1) << 3) + rr);
            uint32_t baddr = brow * ARS + (uint32_t)(ks * 32 + (q & 1) * 16);
            ldsm4(bh[p], sBh + baddr);
            ldsm4(bl[p], sBl + baddr);
        }
#pragma unroll
        for (int mt = 0; mt < 4; mt++) {
            uint32_t arow = (uint32_t)(mbase + mt * 16 + ((q & 1) << 3) + rr);
            uint32_t aaddr = arow * ARS + (uint32_t)(ks * 32 + (q >> 1) * 16);
            uint32_t ah[4], al[4];
            ldsm4(ah, sAh + aaddr);
            ldsm4(al, sAl + aaddr);
#pragma unroll
            for (int nt = 0; nt < NT; nt++) {
                uint32_t b0h[2] = {bh[nt >> 1][(nt & 1) * 2], bh[nt >> 1][(nt & 1) * 2 + 1]};
                uint32_t b0l[2] = {bl[nt >> 1][(nt & 1) * 2], bl[nt >> 1][(nt & 1) * 2 + 1]};
                mma16816(acc[mt][nt], ah, b0h);
                mma16816(acc[mt][nt], al, b0h);
                mma16816(acc[mt][nt], ah, b0l);
            }
        }
    }
}

// ---------------- GEMM kernel: Y = LeakyReLU(A @ W^T + bias), + col stats --------
template <int KD, int NO, int MODE>
__global__ void __launch_bounds__(256, 1)
gemm_mma3(const float* __restrict__ Xext, const float* __restrict__ bext) {
    extern __shared__ char smem[];
    constexpr int NKB = KD / 64;
    constexpr int NT = NO / 32;                 // n-tiles of 8 per warp
    constexpr int AHO = 0, ALO = 128 * ARS, BHO = 2 * 128 * ARS;
    constexpr int BLO = BHO + NO * ARS;
    constexpr int STG = BHO + 2 * NO * ARS;     // bytes per stage
    constexpr int OEPI = 2 * STG;
    const int tid = threadIdx.x, wid = tid >> 5, lane = tid & 31;
    const int bm0 = blockIdx.x * 128;
    const uint32_t sb = smem_u32(smem);

    const __nv_bfloat16* Ah = (MODE == 1) ? g_y1h : g_y2h;
    const __nv_bfloat16* Al = (MODE == 1) ? g_y1l : g_y2l;
    const __nv_bfloat16* Wh = (MODE == 0) ? g_W1h : (MODE == 1 ? g_W2h : g_W3h);
    const __nv_bfloat16* Wl = (MODE == 0) ? g_W1l : (MODE == 1 ? g_W2l : g_W3l);
    const float* bias = (MODE == 0) ? bext : (MODE == 1 ? g_b2e : g_b3e);
    float* gsum = (MODE == 0) ? g_sum1 : (MODE == 1 ? g_sum2 : g_sum3);
    float* gsq  = (MODE == 0) ? g_sq1  : (MODE == 1 ? g_sq2  : g_sq3);

    float* s_bias = (float*)(smem + OEPI);
    float* s_sum  = s_bias + NO;
    float* s_sq   = s_sum + NO;
    if (tid < NO) { s_bias[tid] = __ldg(bias + tid); s_sum[tid] = 0.f; s_sq[tid] = 0.f; }

    float acc[4][NT][4];
#pragma unroll
    for (int i = 0; i < 4; i++)
#pragma unroll
        for (int j = 0; j < NT; j++)
#pragma unroll
            for (int k = 0; k < 4; k++) acc[i][j][k] = 0.f;

    float4 va[8];
    // prologue: 2 stages in flight
    if (MODE == 0) {
        ldgA<KD>(va, Xext, bm0, 0, tid);
        cpTile<NO, KD>(sb + BHO, sb + BLO, Wh, Wl, 0, 0, tid);
        cp_commit();
        if (NKB > 1) {
            cpTile<NO, KD>(sb + STG + BHO, sb + STG + BLO, Wh, Wl, 0, 1, tid);
            cp_commit();
        }
        stsA(smem + AHO, smem + ALO, va, tid);
        if (NKB > 1) ldgA<KD>(va, Xext, bm0, 1, tid);
    } else {
        cpTile<128, KD>(sb + AHO, sb + ALO, Ah, Al, (size_t)bm0, 0, tid);
        cpTile<NO, KD>(sb + BHO, sb + BLO, Wh, Wl, 0, 0, tid);
        cp_commit();
        if (NKB > 1) {
            cpTile<128, KD>(sb + STG + AHO, sb + STG + ALO, Ah, Al, (size_t)bm0, 1, tid);
            cpTile<NO, KD>(sb + STG + BHO, sb + STG + BLO, Wh, Wl, 0, 1, tid);
            cp_commit();
        }
    }

#pragma unroll
    for (int kb = 0; kb < NKB; kb++) {
        const int cur = (kb & 1) * STG;
        const int nxt = ((kb + 1) & 1) * STG;
        if (kb + 1 < NKB) cp_wait1(); else cp_wait0();
        __syncthreads();
        if (MODE == 0) {
            if (kb + 1 < NKB) stsA(smem + nxt + AHO, smem + nxt + ALO, va, tid);
            if (kb + 2 < NKB) ldgA<KD>(va, Xext, bm0, kb + 2, tid);
        }
        computeStage<NT>(sb + cur + AHO, sb + cur + ALO, sb + cur + BHO, sb + cur + BLO,
                         acc, wid, lane);
        __syncthreads();
        if (kb + 2 < NKB) {
            if (MODE != 0)
                cpTile<128, KD>(sb + cur + AHO, sb + cur + ALO, Ah, Al, (size_t)bm0, kb + 2, tid);
            cpTile<NO, KD>(sb + cur + BHO, sb + cur + BLO, Wh, Wl, 0, kb + 2, tid);
            cp_commit();
        }
    }

    // epilogue: bias + leaky + store (split planes / fp32) + stats
    const int mbase = (wid >> 2) * 64;
    const int wn = (wid & 3) * (NT * 8);
    float csum[NT][2], csq[NT][2];
#pragma unroll
    for (int nt = 0; nt < NT; nt++) { csum[nt][0] = csum[nt][1] = 0.f; csq[nt][0] = csq[nt][1] = 0.f; }

    __nv_bfloat16* YH = (MODE == 0) ? g_y1h : g_y2h;
    __nv_bfloat16* YL = (MODE == 0) ? g_y1l : g_y2l;

#pragma unroll
    for (int mt = 0; mt < 4; mt++) {
        int r0 = bm0 + mbase + mt * 16 + (lane >> 2);
        int r1 = r0 + 8;
#pragma unroll
        for (int nt = 0; nt < NT; nt++) {
            int jl = wn + nt * 8 + (lane & 3) * 2;
            float b0 = s_bias[jl], b1 = s_bias[jl + 1];
            float x0 = acc[mt][nt][0] + b0; x0 = x0 > 0.f ? x0 : SLOPE * x0;
            float x1 = acc[mt][nt][1] + b1; x1 = x1 > 0.f ? x1 : SLOPE * x1;
            float x2 = acc[mt][nt][2] + b0; x2 = x2 > 0.f ? x2 : SLOPE * x2;
            float x3 = acc[mt][nt][3] + b1; x3 = x3 > 0.f ? x3 : SLOPE * x3;
            if (r0 < NROWS) {
                if (MODE < 2) {
                    uint32_t h, l;
                    split2(x0, x1, h, l);
                    *(uint32_t*)(YH + (size_t)r0 * NO + jl) = h;
                    *(uint32_t*)(YL + (size_t)r0 * NO + jl) = l;
                } else {
                    *(float2*)(g_y1 + (size_t)r0 * NO + jl) = make_float2(x0, x1);
                }
                csum[nt][0] += x0; csum[nt][1] += x1;
                csq[nt][0] += x0 * x0; csq[nt][1] += x1 * x1;
            }
            if (r1 < NROWS) {
                if (MODE < 2) {
                    uint32_t h, l;
                    split2(x2, x3, h, l);
                    *(uint32_t*)(YH + (size_t)r1 * NO + jl) = h;
                    *(uint32_t*)(YL + (size_t)r1 * NO + jl) = l;
                } else {
                    *(float2*)(g_y1 + (size_t)r1 * NO + jl) = make_float2(x2, x3);
                }
                csum[nt][0] += x2; csum[nt][1] += x3;
                csq[nt][0] += x2 * x2; csq[nt][1] += x3 * x3;
            }
        }
    }
#pragma unroll
    for (int nt = 0; nt < NT; nt++)
#pragma unroll
        for (int p = 0; p < 2; p++) {
            float s = csum[nt][p], q = csq[nt][p];
            s += __shfl_xor_sync(0xFFFFFFFFu, s, 4);  q += __shfl_xor_sync(0xFFFFFFFFu, q, 4);
            s += __shfl_xor_sync(0xFFFFFFFFu, s, 8);  q += __shfl_xor_sync(0xFFFFFFFFu, q, 8);
            s += __shfl_xor_sync(0xFFFFFFFFu, s, 16); q += __shfl_xor_sync(0xFFFFFFFFu, q, 16);
            if (lane < 4) {
                int col = wn + nt * 8 + lane * 2 + p;
                atomicAdd(&s_sum[col], s);
                atomicAdd(&s_sq[col], q);
            }
        }
    __syncthreads();
    if (tid < NO) {
        atomicAdd(gsum + tid, s_sum[tid]);
        atomicAdd(gsq + tid, s_sq[tid]);
    }
}

// ---------------- small kernels --------------------------------------------------
__global__ void zero_stats_kernel() {
    int t = threadIdx.x;  // 256
    g_sum1[t] = 0.f; g_sq1[t] = 0.f;
    g_sum2[t] = 0.f; g_sq2[t] = 0.f;
    if (t < DOUT) { g_sum3[t] = 0.f; g_sq3[t] = 0.f; }
}

__global__ void splitW1_kernel(const float* __restrict__ W1) {
    int i = blockIdx.x * 256 + threadIdx.x;
    if (i < DH * DIN) {
        float w = W1[i];
        __nv_bfloat16 h = __float2bfloat16(w);
        g_W1h[i] = h;
        g_W1l[i] = __float2bfloat16(w - __bfloat162float(h));
    }
}

// fold BN affine of previous layer into next layer's weights, emit bf16 hi/lo planes.
__global__ void fold_kernel(const float* __restrict__ W, const float* __restrict__ b,
                            const float* __restrict__ g, const float* __restrict__ beta,
                            int layer) {
    int j = threadIdx.x;   // 256 = DH
    int o = blockIdx.x;
    const float* sum = (layer == 1) ? g_sum1 : g_sum2;
    const float* sq  = (layer == 1) ? g_sq1  : g_sq2;

    const float invN = 1.0f / (float)NROWS;
    float mean = sum[j] * invN;
    float var  = sq[j] * invN - mean * mean;
    float a = g[j] * rsqrtf(var + EPSBN);
    float c = beta[j] - mean * a;
    float w = W[o * DH + j];
    float wa = w * a;
    __nv_bfloat16 h = __float2bfloat16(wa);
    __nv_bfloat16 l = __float2bfloat16(wa - __bfloat162float(h));
    if (layer == 1) { g_W2h[o * DH + j] = h; g_W2l[o * DH + j] = l; }
    else            { g_W3h[o * DH + j] = h; g_W3l[o * DH + j] = l; }

    __shared__ float red[DH];
    red[j] = w * c;
    __syncthreads();
    for (int s = DH / 2; s > 0; s >>= 1) {
        if (j < s) red[j] += red[j + s];
        __syncthreads();
    }
    if (j == 0) {
        float be = b[o] + red[0];
        if (layer == 1) g_b2e[o] = be; else g_b3e[o] = be;
    }
}

// fused: BN3 coefficients inline + f = y3*a+c + node_update = affine(mean neighbor y3)
__global__ void gather_affine_kernel(const int* __restrict__ nidx,
                                     const float* __restrict__ g3,
                                     const float* __restrict__ be3,
                                     float* __restrict__ fout,
                                     float* __restrict__ out) {
    __shared__ int sidx[2 * KNEI];
    int tid = threadIdx.x;              // 256 threads = 2 nodes
    int node0 = blockIdx.x * 2;
    if (tid < 2 * KNEI) sidx[tid] = nidx[(size_t)node0 * KNEI + tid];
    __syncthreads();
    int local = tid >> 7;
    int j = tid & (DOUT - 1);
    int node = node0 + local;

    const float invN = 1.0f / (float)NROWS;
    float mean = g_sum3[j] * invN;
    float var  = g_sq3[j] * invN - mean * mean;
    float a = __ldg(g3 + j) * rsqrtf(var + EPSBN);
    float c = __ldg(be3 + j) - mean * a;
    const float* y3 = g_y1;             // device-scope reference (valid)

    fout[(size_t)node * DOUT + j] = y3[(size_t)node * DOUT + j] * a + c;

    float s = 0.f;
#pragma unroll
    for (int k = 0; k < KNEI; k++) {
        int nk = sidx[local * KNEI + k];
        s += __ldg(y3 + (size_t)nk * DOUT + j);
    }
    out[(size_t)node * DOUT + j] = (s * (1.0f / KNEI)) * a + c;
}

// ---------------------------------------------------------------------------------
extern "C" void kernel_launch(void* const* d_in, const int* in_sizes, int n_in,
                              void* d_out, int out_size) {
    const float* X   = (const float*)d_in[0];
    const int*   nid = (const int*)d_in[1];
    const float* W1  = (const float*)d_in[3];
    const float* b1  = (const float*)d_in[4];
    const float* g1  = (const float*)d_in[5];
    const float* be1 = (const float*)d_in[6];
    const float* W2  = (const float*)d_in[7];
    const float* b2  = (const float*)d_in[8];
    const float* g2  = (const float*)d_in[9];
    const float* be2 = (const float*)d_in[10];
    const float* W3  = (const float*)d_in[11];
    const float* b3  = (const float*)d_in[12];
    const float* g3  = (const float*)d_in[13];
    const float* be3 = (const float*)d_in[14];

    float* out  = (float*)d_out;                   // node_update [N, DOUT]
    float* fbuf = out + (size_t)NROWS * DOUT;      // f           [N, DOUT]

    const int mblocks = (NROWS + 127) / 128;       // 782
    const int SM256 = 2 * (2 * 128 * ARS + 2 * 256 * ARS) + 3 * 256 * 4;   // 224256
    const int SM128 = 2 * (2 * 128 * ARS + 2 * 128 * ARS) + 3 * 128 * 4;   // 149drawn

    cudaFuncSetAttribute(gemm_mma3<128, 256, 0>, cudaFuncAttributeMaxDynamicSharedMemorySize, SM256);
    cudaFuncSetAttribute(gemm_mma3<256, 256, 1>, cudaFuncAttributeMaxDynamicSharedMemorySize, SM256);
    cudaFuncSetAttribute(gemm_mma3<256, 128, 2>, cudaFuncAttributeMaxDynamicSharedMemorySize, SM128);

    zero_stats_kernel<<<1, 256>>>();
    splitW1_kernel<<<(DH * DIN + 255) / 256, 256>>>(W1);

    // layer 1: X @ W1^T -> y1 planes (+stats1)
    gemm_mma3<128, 256, 0><<<mblocks, 256, SM256>>>(X, b1);
    fold_kernel<<<DH, DH>>>(W2, b2, g1, be1, 1);
    // layer 2: y1 planes @ W2e^T -> y2 planes (+stats2)
    gemm_mma3<256, 256, 1><<<mblocks, 256, SM256>>>(nullptr, nullptr);
    fold_kernel<<<DOUT, DH>>>(W3, b3, g2, be2, 2);
    // layer 3: y2 planes @ W3e^T -> g_y1 fp32 scratch (raw y3, +stats3)
    gemm_mma3<256, 128, 2><<<mblocks, 256, SM128>>>(nullptr, nullptr);

    // fused BN3 coefficients + affine + neighbor-mean gather
    gather_affine_kernel<<<NROWS / 2, 256>>>(nid, g3, be3, fbuf, out);
}